// round 15
// baseline (speedup 1.0000x reference)
#include <cuda_runtime.h>
#include <cuda_fp16.h>
#include <math.h>
#include <stdint.h>

#define BB 4
#define SS 2048
#define DD 2048
typedef __half f16;

constexpr int BM = 128, BN = 128, BK = 16;
constexpr int SUB_B = 128 * 32;             // one sub-tile: 128 rows x 16 f16 (32B), swizzled
constexpr int STAGE = 3 * SUB_B;            // Af, Al, Bf slots (Al unused when AT==1)
constexpr int NSTAGE = 8;
constexpr int SMEM_TOTAL = NSTAGE * STAGE;  // 98304 (2 CTAs/SM)

// ---------------------------------------------------------------------------
// Scratch (device globals — no allocations allowed)
// ---------------------------------------------------------------------------
__device__ float g_Q [(size_t)BB * SS * DD];
__device__ float g_K [(size_t)BB * SS * DD];
__device__ float g_invf[DD / 2];

// A-side hi/lo where needed; B-side single fp16.
__device__ f16 g_xh [(size_t)BB * SS * DD], g_xl [(size_t)BB * SS * DD];
__device__ f16 g_Wqf[(size_t)DD * DD];
__device__ f16 g_Wkf[(size_t)DD * DD];
__device__ f16 g_Wvf[(size_t)DD * DD];
__device__ f16 g_Wof[(size_t)DD * DD];
__device__ f16 g_Qh [(size_t)BB * SS * DD], g_Ql [(size_t)BB * SS * DD];
__device__ f16 g_Kf [(size_t)BB * SS * DD];
__device__ f16 g_Vtf[(size_t)BB * SS * DD];                      // [b][d][s]
__device__ f16 g_Pf [(size_t)BB * SS * SS];                      // single fp16 P
__device__ f16 g_Cf [(size_t)BB * SS * DD];                      // single fp16 ctx

// ---------------------------------------------------------------------------
// helpers
// ---------------------------------------------------------------------------
__device__ __forceinline__ uint32_t smem_u32(const void* p)
{
    uint32_t a;
    asm("{ .reg .u64 t; cvta.to.shared.u64 t, %1; cvt.u32.u64 %0, t; }"
        : "=r"(a) : "l"(p));
    return a;
}
__device__ __forceinline__ void cp16(uint32_t saddr, const void* g)
{
    asm volatile("cp.async.cg.shared.global [%0], [%1], 16;" :: "r"(saddr), "l"(g));
}
__device__ __forceinline__ void cp_commit() { asm volatile("cp.async.commit_group;"); }
__device__ __forceinline__ void cp_wait4()  { asm volatile("cp.async.wait_group 4;"); }
__device__ __forceinline__ void cp_wait0()  { asm volatile("cp.async.wait_group 0;"); }

__device__ __forceinline__ void ldsm4(uint32_t* r, uint32_t addr)
{
    asm volatile("ldmatrix.sync.aligned.m8n8.x4.shared.b16 {%0,%1,%2,%3}, [%4];\n"
                 : "=r"(r[0]), "=r"(r[1]), "=r"(r[2]), "=r"(r[3]) : "r"(addr));
}
__device__ __forceinline__ void mma16816(float* d, const uint32_t* a, const uint32_t* b)
{
    asm volatile(
        "mma.sync.aligned.m16n8k16.row.col.f32.f16.f16.f32 "
        "{%0,%1,%2,%3}, {%4,%5,%6,%7}, {%8,%9}, {%0,%1,%2,%3};\n"
        : "+f"(d[0]), "+f"(d[1]), "+f"(d[2]), "+f"(d[3])
        : "r"(a[0]), "r"(a[1]), "r"(a[2]), "r"(a[3]), "r"(b[0]), "r"(b[1]));
}
__device__ __forceinline__ void splitf(float v, f16& h, f16& l)
{
    h = __float2half(v);
    l = __float2half(v - __half2float(h));
}

// Swizzled smem byte offset within one sub-tile (validated in R10).
__device__ __forceinline__ uint32_t swz_off(int r, int c16)
{
    return (uint32_t)(r * 32 + ((c16 ^ ((r >> 2) & 1)) << 4));
}

// ---------------------------------------------------------------------------
// fp16 GEMM body (256 thr, 2 CTAs/SM, 8-stage BK=16 cp.async, 2 chunks/barrier):
//   C[m,n] = sum_k A[m,k]*B[n,k]
//   AT=2: acc = Ah*Bf + Al*Bf (A split hi/lo).  AT=1: acc = Af*Bf.
// EPI: 0 = fp32 C (+bias/scale/causal-zero), 1 = single f16 Cf,
//      2 = single f16 + transpose per batch (Vt), with bias.
// ---------------------------------------------------------------------------
template <int EPI, int AT>
__device__ __forceinline__ void gemm_body(
    const f16* __restrict__ Ah, const f16* __restrict__ Al,
    const f16* __restrict__ Bf,
    const float* __restrict__ bias, float* __restrict__ C,
    f16* __restrict__ Cf,
    int N, int K, float scale, int causal, int triK,
    int m0, int n0, char* dsm)
{
    const uint32_t smem_base = smem_u32(dsm);

    if (causal && n0 > m0 + BM - 1) return;
    const int kEnd = triK ? (m0 + BM) : K;
    const int nSteps = kEnd / BK;           // >= 8 and even for all our shapes

    const int t = threadIdx.x;
    const int lane = t & 31, warp = t >> 5;
    const int wm = warp >> 1;   // 0..3 -> 32 rows
    const int wn = warp & 1;    // 0..1 -> 64 cols

    float acc[2][8][4];
#pragma unroll
    for (int i = 0; i < 2; i++)
#pragma unroll
        for (int j = 0; j < 8; j++)
#pragma unroll
            for (int q = 0; q < 4; q++) acc[i][j][q] = 0.f;

    // fill one 16-k stage (ks clamped by caller): AT cp16 for A + 1 for B
    const int f_row = t >> 1;          // 0..127
    const int f_c16 = t & 1;           // 0..1
    const uint32_t f_so = swz_off(f_row, f_c16);
    auto fill = [&](int buf, int ks) {
        const uint32_t sb = smem_base + buf * STAGE;
        const long long g = (long long)f_row * K + ks * BK + f_c16 * 8;
        cp16(sb + 0 * SUB_B + f_so, Ah + (long long)m0 * K + g);
        if (AT == 2) cp16(sb + 1 * SUB_B + f_so, Al + (long long)m0 * K + g);
        cp16(sb + 2 * SUB_B + f_so, Bf + (long long)n0 * K + g);
    };

    // ldmatrix lane->element mapping (validated since R2)
    const int a_r = (lane & 7) + ((lane >> 3) & 1) * 8;
    const int a_h = lane >> 4;                 // col half 0/1
    const int b_r = (lane & 7) + ((lane >> 4) & 1) * 8;
    const int b_h = (lane >> 3) & 1;

    auto compute = [&](int buf) {
        const uint32_t sb = smem_base + buf * STAGE;
        const uint32_t bAh = sb, bAl = sb + SUB_B, bBf = sb + 2 * SUB_B;

        uint32_t ah[2][4], al[2][4];
#pragma unroll
        for (int mt = 0; mt < 2; mt++) {
            const int R = wm * 32 + mt * 16 + a_r;
            const uint32_t off = swz_off(R, a_h);
            ldsm4(ah[mt], bAh + off);
            if (AT == 2) ldsm4(al[mt], bAl + off);
        }
#pragma unroll
        for (int np = 0; np < 4; np++) {
            const int Rb = wn * 64 + np * 16 + b_r;
            const uint32_t off = swz_off(Rb, b_h);
            uint32_t bf[4];
            ldsm4(bf, bBf + off);
#pragma unroll
            for (int mt = 0; mt < 2; mt++) {
                mma16816(acc[mt][2 * np], ah[mt], bf);
                if (AT == 2) mma16816(acc[mt][2 * np], al[mt], bf);
                mma16816(acc[mt][2 * np + 1], ah[mt], bf + 2);
                if (AT == 2) mma16816(acc[mt][2 * np + 1], al[mt], bf + 2);
            }
        }
    };

    // prologue: 6 stages in flight (one commit each; ks always valid, nSteps>=8)
#pragma unroll
    for (int s = 0; s < 6; s++) {
        fill(s, s);
        cp_commit();
    }

    // main loop: 2 chunks per wait+barrier. Fills are ALWAYS issued (ks clamped
    // to nSteps-1 into an already-consumed buffer) so cp.async group accounting
    // stays exact at the tail.
    for (int c0 = 0; c0 < nSteps; c0 += 2) {
        cp_wait4();                 // stages c0, c0+1 complete
        __syncthreads();            // all warps past compute(c0-1); old buffers free

        {
            const int k6 = c0 + 6 < nSteps ? c0 + 6 : nSteps - 1;
            fill((c0 + 6) & 7, k6);
            cp_commit();
            const int k7 = c0 + 7 < nSteps ? c0 + 7 : nSteps - 1;
            fill((c0 + 7) & 7, k7);
            cp_commit();
        }

        compute(c0 & 7);
        compute((c0 + 1) & 7);      // nSteps is even for all shapes
    }

    // ---------------- epilogue ----------------
    if (EPI == 2) {
        cp_wait0();
        __syncthreads();
        f16* Th = reinterpret_cast<f16*>(dsm);                // [128][136]
#pragma unroll
        for (int mt = 0; mt < 2; mt++) {
            const int li0 = wm * 32 + mt * 16 + (lane >> 2);
#pragma unroll
            for (int nt = 0; nt < 8; nt++) {
                const int lj = wn * 64 + nt * 8 + (lane & 3) * 2;
#pragma unroll
                for (int h = 0; h < 2; h++) {
                    const int li = li0 + h * 8;
#pragma unroll
                    for (int cc = 0; cc < 2; cc++) {
                        float v = acc[mt][nt][h * 2 + cc];
                        if (bias) v += bias[n0 + lj + cc];
                        Th[(lj + cc) * 136 + li] = __float2half(v);
                    }
                }
            }
        }
        __syncthreads();
        {
            const int j = t & 127;           // local n (= d) row
            const int hf = t >> 7;           // which 64-element half of the row
            const int bb = m0 >> 11;         // SS = 2048
            const int s0 = m0 & (SS - 1);
            const f16* src = Th + j * 136 + hf * 64;
            f16* dst = Cf + ((long long)bb * DD + n0 + j) * SS + s0 + hf * 64;
#pragma unroll
            for (int i = 0; i < 64; i += 8)
                *reinterpret_cast<uint4*>(dst + i) =
                    *reinterpret_cast<const uint4*>(src + i);
        }
        return;
    }

#pragma unroll
    for (int mt = 0; mt < 2; mt++) {
        const int gi0 = m0 + wm * 32 + mt * 16 + (lane >> 2);
#pragma unroll
        for (int nt = 0; nt < 8; nt++) {
            const int gj = n0 + wn * 64 + nt * 8 + (lane & 3) * 2;
            const float* d = acc[mt][nt];
#pragma unroll
            for (int h = 0; h < 2; h++) {
                const int gi = gi0 + h * 8;
                float v0 = d[h * 2 + 0] * scale;
                float v1 = d[h * 2 + 1] * scale;
                if (bias) { v0 += bias[gj]; v1 += bias[gj + 1]; }
                if (causal) {
                    if (gj > gi) v0 = 0.f;
                    if (gj + 1 > gi) v1 = 0.f;
                }
                if (EPI == 0) {
                    *reinterpret_cast<float2*>(&C[(long long)gi * N + gj]) =
                        make_float2(v0, v1);
                } else {
                    __half2 ph;
                    ph.x = __float2half(v0);
                    ph.y = __float2half(v1);
                    *reinterpret_cast<__half2*>(&Cf[(long long)gi * N + gj]) = ph;
                }
            }
        }
    }
}

// ---------------------------------------------------------------------------
// Merged Q/K/V projection: grid z selects projection.
// ---------------------------------------------------------------------------
__global__ __launch_bounds__(256, 2) void proj3_kernel(
    const f16* __restrict__ xh, const f16* __restrict__ xl,
    const f16* __restrict__ Wqf, const float* __restrict__ bq, float* __restrict__ Q,
    const f16* __restrict__ Wkf, const float* __restrict__ bk, float* __restrict__ Kt,
    const f16* __restrict__ Wvf, const float* __restrict__ bv,
    f16* __restrict__ Vtf)
{
    extern __shared__ __align__(128) char dsm[];
    const int m0 = blockIdx.y * BM;
    const int n0 = blockIdx.x * BN;
    const int z = blockIdx.z;
    if (z == 0)
        gemm_body<0, 2>(xh, xl, Wqf, bq, Q, nullptr,
                        DD, DD, 1.f, 0, 0, m0, n0, dsm);
    else if (z == 1)
        gemm_body<0, 2>(xh, xl, Wkf, bk, Kt, nullptr,
                        DD, DD, 1.f, 0, 0, m0, n0, dsm);
    else
        gemm_body<2, 2>(xh, xl, Wvf, bv, nullptr, Vtf,
                        DD, DD, 1.f, 0, 0, m0, n0, dsm);
}

__global__ __launch_bounds__(256, 2) void scores_kernel(
    const f16* __restrict__ Qh, const f16* __restrict__ Ql,
    const f16* __restrict__ Kf,
    f16* __restrict__ Pf, float scale)
{
    extern __shared__ __align__(128) char dsm[];
    const long long zd = (long long)blockIdx.z * SS * DD;
    const long long zs = (long long)blockIdx.z * SS * SS;
    gemm_body<1, 2>(Qh + zd, Ql + zd, Kf + zd, nullptr, nullptr,
                    Pf + zs, SS, DD, scale, 1, 0,
                    blockIdx.y * BM, blockIdx.x * BN, dsm);
}

__global__ __launch_bounds__(256, 2) void pv_kernel(
    const f16* __restrict__ Pf, const f16* __restrict__ Vtf,
    f16* __restrict__ Cf)
{
    extern __shared__ __align__(128) char dsm[];
    const long long zs = (long long)blockIdx.z * SS * SS;
    const long long zd = (long long)blockIdx.z * SS * DD;
    gemm_body<1, 1>(Pf + zs, nullptr, Vtf + zd, nullptr, nullptr,
                    Cf + zd, DD, SS, 1.f, 0, 1,
                    blockIdx.y * BM, blockIdx.x * BN, dsm);
}

__global__ __launch_bounds__(256, 2) void outproj_kernel(
    const f16* __restrict__ Cf, const f16* __restrict__ Wof,
    const float* __restrict__ bo, float* __restrict__ out)
{
    extern __shared__ __align__(128) char dsm[];
    gemm_body<0, 1>(Cf, nullptr, Wof, bo, out, nullptr,
                    DD, DD, 1.f, 0, 0, blockIdx.y * BM, blockIdx.x * BN, dsm);
}

// ---------------------------------------------------------------------------
// Fused split: x -> f16 hi/lo, weights -> single f16; also fills invf.
// ---------------------------------------------------------------------------
constexpr long long N4X = (long long)BB * SS * DD / 4;
constexpr long long N4W = (long long)DD * DD / 4;

__global__ void split_all_kernel(
    const float* __restrict__ x,
    const float* __restrict__ Wq, const float* __restrict__ Wk,
    const float* __restrict__ Wv, const float* __restrict__ Wo,
    f16* __restrict__ xh, f16* __restrict__ xl,
    f16* __restrict__ Wqf, f16* __restrict__ Wkf,
    f16* __restrict__ Wvf, f16* __restrict__ Wof,
    float* __restrict__ invf)
{
    const long long i = (long long)blockIdx.x * blockDim.x + threadIdx.x;
    if (i < DD / 2)
        invf[i] = (float)exp(-(double)i * (9.210340371976184 / (double)(DD / 2)));

    if (i < N4X) {
        float4 v = *reinterpret_cast<const float4*>(x + i * 4);
        f16 h[4], l[4];
        splitf(v.x, h[0], l[0]); splitf(v.y, h[1], l[1]);
        splitf(v.z, h[2], l[2]); splitf(v.w, h[3], l[3]);
        *reinterpret_cast<uint2*>(xh + i * 4) = *reinterpret_cast<uint2*>(h);
        *reinterpret_cast<uint2*>(xl + i * 4) = *reinterpret_cast<uint2*>(l);
        return;
    }
    const float* src;
    f16* dst;
    long long o = i - N4X;
    if (o < N4W)          { src = Wq; dst = Wqf; }
    else if (o < 2 * N4W) { src = Wk; dst = Wkf; o -= N4W; }
    else if (o < 3 * N4W) { src = Wv; dst = Wvf; o -= 2 * N4W; }
    else if (o < 4 * N4W) { src = Wo; dst = Wof; o -= 3 * N4W; }
    else return;

    float4 v = *reinterpret_cast<const float4*>(src + o * 4);
    f16 h[4];
    h[0] = __float2half(v.x); h[1] = __float2half(v.y);
    h[2] = __float2half(v.z); h[3] = __float2half(v.w);
    *reinterpret_cast<uint2*>(dst + o * 4) = *reinterpret_cast<uint2*>(h);
}

// ---------------------------------------------------------------------------
// RoPE: rotate fp32 Q/K pairs; Q -> f16 hi/lo (A-side), K -> single f16.
// ---------------------------------------------------------------------------
__global__ void rope_split_kernel(const float* __restrict__ Q,
                                  const float* __restrict__ Kt,
                                  const float* __restrict__ invf,
                                  f16* __restrict__ Qh, f16* __restrict__ Ql,
                                  f16* __restrict__ Kf)
{
    const int half = DD / 2;
    long long idx = (long long)blockIdx.x * blockDim.x + threadIdx.x;
    const long long total = (long long)BB * SS * half;
    if (idx >= total) return;

    const int i = (int)(idx % half);
    const long long bs = idx / half;
    const int s = (int)(bs % SS);

    const float ang = (float)s * invf[i];
    float sn, cs;
    sincosf(ang, &sn, &cs);

    const long long o = bs * DD;
    const float q1 = Q[o + i], q2 = Q[o + i + half];
    const float k1 = Kt[o + i], k2 = Kt[o + i + half];
    const float qa = q1 * cs - q2 * sn, qb = q1 * sn + q2 * cs;
    const float ka = k1 * cs - k2 * sn, kb = k1 * sn + k2 * cs;

    f16 h, l;
    splitf(qa, h, l); Qh[o + i] = h;        Ql[o + i] = l;
    splitf(qb, h, l); Qh[o + i + half] = h; Ql[o + i + half] = l;
    Kf[o + i] = __float2half(ka);
    Kf[o + i + half] = __float2half(kb);
}

// ---------------------------------------------------------------------------
// Register-resident causal softmax over single-f16 scores (in place).
// ---------------------------------------------------------------------------
__inline__ __device__ float warpMax(float v)
{
    for (int o = 16; o; o >>= 1) v = fmaxf(v, __shfl_xor_sync(0xffffffffu, v, o));
    return v;
}
__inline__ __device__ float warpSum(float v)
{
    for (int o = 16; o; o >>= 1) v += __shfl_xor_sync(0xffffffffu, v, o);
    return v;
}

__global__ __launch_bounds__(256) void softmax_kernel(f16* __restrict__ Pf)
{
    const int i = blockIdx.x;
    const int b = blockIdx.y;
    const long long off = ((long long)b * SS + i) * SS;
    const int len = i + 1;
    const int t = threadIdx.x;
    const int lane = t & 31, w = t >> 5;

    __shared__ float sh[8];
    __shared__ float s_bcast;

    float s[8];
    float m = -INFINITY;
#pragma unroll
    for (int p = 0; p < 8; p++) {
        const int j = t + p * 256;
        if (j < len) {
            s[p] = __half2float(Pf[off + j]);
            m = fmaxf(m, s[p]);
        }
    }
    m = warpMax(m);
    if (lane == 0) sh[w] = m;
    __syncthreads();
    if (t == 0) {
        float mm = sh[0];
        for (int k = 1; k < 8; k++) mm = fmaxf(mm, sh[k]);
        s_bcast = mm;
    }
    __syncthreads();
    m = s_bcast;
    __syncthreads();

    float sum = 0.f;
#pragma unroll
    for (int p = 0; p < 8; p++) {
        const int j = t + p * 256;
        if (j < len) {
            s[p] = expf(s[p] - m);
            sum += s[p];
        }
    }
    sum = warpSum(sum);
    if (lane == 0) sh[w] = sum;
    __syncthreads();
    if (t == 0) {
        float ss = 0.f;
        for (int k = 0; k < 8; k++) ss += sh[k];
        s_bcast = ss;
    }
    __syncthreads();
    const float inv = 1.f / s_bcast;

#pragma unroll
    for (int p = 0; p < 8; p++) {
        const int j = t + p * 256;
        if (j < len) Pf[off + j] = __float2half(s[p] * inv);
    }
}

// ---------------------------------------------------------------------------
extern "C" void kernel_launch(void* const* d_in, const int* in_sizes, int n_in,
                              void* d_out, int out_size)
{
    const float* x  = (const float*)d_in[0];
    // d_in[1] = mask — analytic
    const float* Wq = (const float*)d_in[2];
    const float* bq = (const float*)d_in[3];
    const float* Wk = (const float*)d_in[4];
    const float* bk = (const float*)d_in[5];
    const float* Wv = (const float*)d_in[6];
    const float* bv = (const float*)d_in[7];
    const float* Wo = (const float*)d_in[8];
    const float* bo = (const float*)d_in[9];
    float* out = (float*)d_out;

    float *pQ, *pK, *pInvf;
    cudaGetSymbolAddress((void**)&pQ, g_Q);
    cudaGetSymbolAddress((void**)&pK, g_K);
    cudaGetSymbolAddress((void**)&pInvf, g_invf);

    f16 *xh, *xl, *Wqf, *Wkf, *Wvf, *Wof;
    f16 *Qh, *Ql, *Kf, *Vtf, *Pf, *Cf;
    cudaGetSymbolAddress((void**)&xh, g_xh);   cudaGetSymbolAddress((void**)&xl, g_xl);
    cudaGetSymbolAddress((void**)&Wqf, g_Wqf); cudaGetSymbolAddress((void**)&Wkf, g_Wkf);
    cudaGetSymbolAddress((void**)&Wvf, g_Wvf); cudaGetSymbolAddress((void**)&Wof, g_Wof);
    cudaGetSymbolAddress((void**)&Qh, g_Qh);   cudaGetSymbolAddress((void**)&Ql, g_Ql);
    cudaGetSymbolAddress((void**)&Kf, g_Kf);
    cudaGetSymbolAddress((void**)&Vtf, g_Vtf);
    cudaGetSymbolAddress((void**)&Pf, g_Pf);
    cudaGetSymbolAddress((void**)&Cf, g_Cf);

    cudaFuncSetAttribute(proj3_kernel,   cudaFuncAttributeMaxDynamicSharedMemorySize, SMEM_TOTAL);
    cudaFuncSetAttribute(scores_kernel,  cudaFuncAttributeMaxDynamicSharedMemorySize, SMEM_TOTAL);
    cudaFuncSetAttribute(pv_kernel,      cudaFuncAttributeMaxDynamicSharedMemorySize, SMEM_TOTAL);
    cudaFuncSetAttribute(outproj_kernel, cudaFuncAttributeMaxDynamicSharedMemorySize, SMEM_TOTAL);

    const dim3 blk(256);

    // 1) fused split of x and all weights (+ invf table)
    {
        const long long n4 = N4X + 4 * N4W;
        split_all_kernel<<<(int)((n4 + 255) / 256), 256>>>(
            x, Wq, Wk, Wv, Wo, xh, xl, Wqf, Wkf, Wvf, Wof, pInvf);
    }

    // 2) merged Q/K/V projections
    proj3_kernel<<<dim3(DD / BN, (BB * SS) / BM, 3), blk, SMEM_TOTAL>>>(
        xh, xl, Wqf, bq, pQ, Wkf, bk, pK, Wvf, bv, Vtf);

    // 3) RoPE + split Q / round K
    {
        const long long total = (long long)BB * SS * (DD / 2);
        rope_split_kernel<<<(int)((total + 255) / 256), 256>>>(pQ, pK, pInvf,
                                                               Qh, Ql, Kf);
    }

    // 4) scores = Q K^T / sqrt(D), causal -> single f16 P
    const float scale = 0.022097086912079608f;  // 1/sqrt(2048)
    scores_kernel<<<dim3(SS / BN, SS / BM, BB), blk, SMEM_TOTAL>>>(
        Qh, Ql, Kf, Pf, scale);

    // 5) register softmax on P (in place)
    softmax_kernel<<<dim3(SS, BB), 256>>>(Pf);

    // 6) ctx = P V (triangular K) -> single f16 ctx
    pv_kernel<<<dim3(DD / BN, SS / BM, BB), blk, SMEM_TOTAL>>>(Pf, Vtf, Cf);

    // 7) out = ctx Wo^T + bo
    outproj_kernel<<<dim3(DD / BN, (BB * SS) / BM, 1), blk, SMEM_TOTAL>>>(
        Cf, Wof, bo, out);
}

// round 16
// speedup vs baseline: 1.1925x; 1.1925x over previous
#include <cuda_runtime.h>
#include <cuda_fp16.h>
#include <math.h>
#include <stdint.h>

#define BB 4
#define SS 2048
#define DD 2048
typedef __half f16;

constexpr int BM = 128, BN = 128, BK = 16;
constexpr int SUB_B = 128 * 32;             // one sub-tile: 128 rows x 16 f16 (32B), swizzled
constexpr int STAGE = 3 * SUB_B;            // Af, Al, Bf slots (Al unused when AT==1)
constexpr int NSTAGE = 8;
constexpr int PIPE_D = 7;                   // stages in flight (R13-proven)
constexpr int SMEM_TOTAL = NSTAGE * STAGE;  // 98304 (2 CTAs/SM)

// ---------------------------------------------------------------------------
// Scratch (device globals — no allocations allowed)
// ---------------------------------------------------------------------------
__device__ float g_Q [(size_t)BB * SS * DD];
__device__ float g_K [(size_t)BB * SS * DD];
__device__ float g_invf[DD / 2];

// A-side hi/lo where needed; B-side single fp16.
__device__ f16 g_xh [(size_t)BB * SS * DD], g_xl [(size_t)BB * SS * DD];
__device__ f16 g_Wqf[(size_t)DD * DD];
__device__ f16 g_Wkf[(size_t)DD * DD];
__device__ f16 g_Wvf[(size_t)DD * DD];
__device__ f16 g_Wof[(size_t)DD * DD];
__device__ f16 g_Qh [(size_t)BB * SS * DD], g_Ql [(size_t)BB * SS * DD];
__device__ f16 g_Kf [(size_t)BB * SS * DD];
__device__ f16 g_Vtf[(size_t)BB * SS * DD];                      // [b][d][s]
__device__ f16 g_Pf [(size_t)BB * SS * SS];                      // single fp16 P
__device__ f16 g_Cf [(size_t)BB * SS * DD];                      // single fp16 ctx

// ---------------------------------------------------------------------------
// helpers
// ---------------------------------------------------------------------------
__device__ __forceinline__ uint32_t smem_u32(const void* p)
{
    uint32_t a;
    asm("{ .reg .u64 t; cvta.to.shared.u64 t, %1; cvt.u32.u64 %0, t; }"
        : "=r"(a) : "l"(p));
    return a;
}
__device__ __forceinline__ void cp16(uint32_t saddr, const void* g)
{
    asm volatile("cp.async.cg.shared.global [%0], [%1], 16;" :: "r"(saddr), "l"(g));
}
__device__ __forceinline__ void cp_commit() { asm volatile("cp.async.commit_group;"); }
__device__ __forceinline__ void cp_waitD()  { asm volatile("cp.async.wait_group 6;"); }
__device__ __forceinline__ void cp_wait0()  { asm volatile("cp.async.wait_group 0;"); }

__device__ __forceinline__ void ldsm4(uint32_t* r, uint32_t addr)
{
    asm volatile("ldmatrix.sync.aligned.m8n8.x4.shared.b16 {%0,%1,%2,%3}, [%4];\n"
                 : "=r"(r[0]), "=r"(r[1]), "=r"(r[2]), "=r"(r[3]) : "r"(addr));
}
__device__ __forceinline__ void mma16816(float* d, const uint32_t* a, const uint32_t* b)
{
    asm volatile(
        "mma.sync.aligned.m16n8k16.row.col.f32.f16.f16.f32 "
        "{%0,%1,%2,%3}, {%4,%5,%6,%7}, {%8,%9}, {%0,%1,%2,%3};\n"
        : "+f"(d[0]), "+f"(d[1]), "+f"(d[2]), "+f"(d[3])
        : "r"(a[0]), "r"(a[1]), "r"(a[2]), "r"(a[3]), "r"(b[0]), "r"(b[1]));
}
__device__ __forceinline__ void splitf(float v, f16& h, f16& l)
{
    h = __float2half(v);
    l = __float2half(v - __half2float(h));
}

// Swizzled smem byte offset within one sub-tile (validated in R10).
__device__ __forceinline__ uint32_t swz_off(int r, int c16)
{
    return (uint32_t)(r * 32 + ((c16 ^ ((r >> 2) & 1)) << 4));
}

// ---------------------------------------------------------------------------
// fp16 GEMM body (256 thr, 2 CTAs/SM, 8-stage BK=16 cp.async, R13 mainloop):
//   C[m,n] = sum_k A[m,k]*B[n,k]
//   AT=2: acc = Ah*Bf + Al*Bf (A split hi/lo).  AT=1: acc = Af*Bf.
// EPI: 0 = fp32 C (+bias/scale/causal-zero), 1 = single f16 Cf,
//      2 = single f16 + transpose per batch (Vt), with bias.
// ---------------------------------------------------------------------------
template <int EPI, int AT>
__device__ __forceinline__ void gemm_body(
    const f16* __restrict__ Ah, const f16* __restrict__ Al,
    const f16* __restrict__ Bf,
    const float* __restrict__ bias, float* __restrict__ C,
    f16* __restrict__ Cf,
    int N, int K, float scale, int causal, int triK,
    int m0, int n0, char* dsm)
{
    const uint32_t smem_base = smem_u32(dsm);

    if (causal && n0 > m0 + BM - 1) return;
    const int kEnd = triK ? (m0 + BM) : K;
    const int nSteps = kEnd / BK;           // >= 8 for all our shapes

    const int t = threadIdx.x;
    const int lane = t & 31, warp = t >> 5;
    const int wm = warp >> 1;   // 0..3 -> 32 rows
    const int wn = warp & 1;    // 0..1 -> 64 cols

    float acc[2][8][4];
#pragma unroll
    for (int i = 0; i < 2; i++)
#pragma unroll
        for (int j = 0; j < 8; j++)
#pragma unroll
            for (int q = 0; q < 4; q++) acc[i][j][q] = 0.f;

    // fill one 16-k stage: AT cp16 for A + 1 for B
    const int f_row = t >> 1;          // 0..127
    const int f_c16 = t & 1;           // 0..1
    const uint32_t f_so = swz_off(f_row, f_c16);
    auto fill = [&](int buf, int ks) {
        const uint32_t sb = smem_base + buf * STAGE;
        const long long g = (long long)f_row * K + ks * BK + f_c16 * 8;
        cp16(sb + 0 * SUB_B + f_so, Ah + (long long)m0 * K + g);
        if (AT == 2) cp16(sb + 1 * SUB_B + f_so, Al + (long long)m0 * K + g);
        cp16(sb + 2 * SUB_B + f_so, Bf + (long long)n0 * K + g);
    };

    // ldmatrix lane->element mapping (validated since R2)
    const int a_r = (lane & 7) + ((lane >> 3) & 1) * 8;
    const int a_h = lane >> 4;                 // col half 0/1
    const int b_r = (lane & 7) + ((lane >> 4) & 1) * 8;
    const int b_h = (lane >> 3) & 1;

    // prologue: PIPE_D stages in flight
#pragma unroll
    for (int s = 0; s < PIPE_D; s++) {
        if (s < nSteps) fill(s, s);
        cp_commit();
    }

    int bufc = 0;            // c % NSTAGE
    int buff = PIPE_D;       // (c + PIPE_D) % NSTAGE
    for (int c = 0; c < nSteps; c++) {
        cp_waitD();                 // group c complete
        __syncthreads();            // all warps past compute(c-1); buffer buff reusable

        if (c + PIPE_D < nSteps) fill(buff, c + PIPE_D);
        cp_commit();

        const uint32_t sb = smem_base + bufc * STAGE;
        const uint32_t bAh = sb, bAl = sb + SUB_B, bBf = sb + 2 * SUB_B;

        uint32_t ah[2][4], al[2][4];
#pragma unroll
        for (int mt = 0; mt < 2; mt++) {
            const int R = wm * 32 + mt * 16 + a_r;
            const uint32_t off = swz_off(R, a_h);
            ldsm4(ah[mt], bAh + off);
            if (AT == 2) ldsm4(al[mt], bAl + off);
        }
#pragma unroll
        for (int np = 0; np < 4; np++) {
            const int Rb = wn * 64 + np * 16 + b_r;
            const uint32_t off = swz_off(Rb, b_h);
            uint32_t bf[4];
            ldsm4(bf, bBf + off);
#pragma unroll
            for (int mt = 0; mt < 2; mt++) {
                mma16816(acc[mt][2 * np], ah[mt], bf);
                if (AT == 2) mma16816(acc[mt][2 * np], al[mt], bf);
                mma16816(acc[mt][2 * np + 1], ah[mt], bf + 2);
                if (AT == 2) mma16816(acc[mt][2 * np + 1], al[mt], bf + 2);
            }
        }

        if (++bufc == NSTAGE) bufc = 0;
        if (++buff == NSTAGE) buff = 0;
    }

    // ---------------- epilogue ----------------
    if (EPI == 2) {
        cp_wait0();
        __syncthreads();
        f16* Th = reinterpret_cast<f16*>(dsm);                // [128][136]
#pragma unroll
        for (int mt = 0; mt < 2; mt++) {
            const int li0 = wm * 32 + mt * 16 + (lane >> 2);
#pragma unroll
            for (int nt = 0; nt < 8; nt++) {
                const int lj = wn * 64 + nt * 8 + (lane & 3) * 2;
#pragma unroll
                for (int h = 0; h < 2; h++) {
                    const int li = li0 + h * 8;
#pragma unroll
                    for (int cc = 0; cc < 2; cc++) {
                        float v = acc[mt][nt][h * 2 + cc];
                        if (bias) v += bias[n0 + lj + cc];
                        Th[(lj + cc) * 136 + li] = __float2half(v);
                    }
                }
            }
        }
        __syncthreads();
        {
            const int j = t & 127;           // local n (= d) row
            const int hf = t >> 7;           // which 64-element half of the row
            const int bb = m0 >> 11;         // SS = 2048
            const int s0 = m0 & (SS - 1);
            const f16* src = Th + j * 136 + hf * 64;
            f16* dst = Cf + ((long long)bb * DD + n0 + j) * SS + s0 + hf * 64;
#pragma unroll
            for (int i = 0; i < 64; i += 8)
                *reinterpret_cast<uint4*>(dst + i) =
                    *reinterpret_cast<const uint4*>(src + i);
        }
        return;
    }

#pragma unroll
    for (int mt = 0; mt < 2; mt++) {
        const int gi0 = m0 + wm * 32 + mt * 16 + (lane >> 2);
#pragma unroll
        for (int nt = 0; nt < 8; nt++) {
            const int gj = n0 + wn * 64 + nt * 8 + (lane & 3) * 2;
            const float* d = acc[mt][nt];
#pragma unroll
            for (int h = 0; h < 2; h++) {
                const int gi = gi0 + h * 8;
                float v0 = d[h * 2 + 0] * scale;
                float v1 = d[h * 2 + 1] * scale;
                if (bias) { v0 += bias[gj]; v1 += bias[gj + 1]; }
                if (causal) {
                    if (gj > gi) v0 = 0.f;
                    if (gj + 1 > gi) v1 = 0.f;
                }
                if (EPI == 0) {
                    *reinterpret_cast<float2*>(&C[(long long)gi * N + gj]) =
                        make_float2(v0, v1);
                } else {
                    __half2 ph;
                    ph.x = __float2half(v0);
                    ph.y = __float2half(v1);
                    *reinterpret_cast<__half2*>(&Cf[(long long)gi * N + gj]) = ph;
                }
            }
        }
    }
}

// ---------------------------------------------------------------------------
// Merged Q/K/V projection: grid z selects projection.
// ---------------------------------------------------------------------------
__global__ __launch_bounds__(256, 2) void proj3_kernel(
    const f16* __restrict__ xh, const f16* __restrict__ xl,
    const f16* __restrict__ Wqf, const float* __restrict__ bq, float* __restrict__ Q,
    const f16* __restrict__ Wkf, const float* __restrict__ bk, float* __restrict__ Kt,
    const f16* __restrict__ Wvf, const float* __restrict__ bv,
    f16* __restrict__ Vtf)
{
    extern __shared__ __align__(128) char dsm[];
    const int m0 = blockIdx.y * BM;
    const int n0 = blockIdx.x * BN;
    const int z = blockIdx.z;
    if (z == 0)
        gemm_body<0, 2>(xh, xl, Wqf, bq, Q, nullptr,
                        DD, DD, 1.f, 0, 0, m0, n0, dsm);
    else if (z == 1)
        gemm_body<0, 2>(xh, xl, Wkf, bk, Kt, nullptr,
                        DD, DD, 1.f, 0, 0, m0, n0, dsm);
    else
        gemm_body<2, 2>(xh, xl, Wvf, bv, nullptr, Vtf,
                        DD, DD, 1.f, 0, 0, m0, n0, dsm);
}

__global__ __launch_bounds__(256, 2) void scores_kernel(
    const f16* __restrict__ Qh, const f16* __restrict__ Ql,
    const f16* __restrict__ Kf,
    f16* __restrict__ Pf, float scale)
{
    extern __shared__ __align__(128) char dsm[];
    const long long zd = (long long)blockIdx.z * SS * DD;
    const long long zs = (long long)blockIdx.z * SS * SS;
    gemm_body<1, 2>(Qh + zd, Ql + zd, Kf + zd, nullptr, nullptr,
                    Pf + zs, SS, DD, scale, 1, 0,
                    blockIdx.y * BM, blockIdx.x * BN, dsm);
}

__global__ __launch_bounds__(256, 2) void pv_kernel(
    const f16* __restrict__ Pf, const f16* __restrict__ Vtf,
    f16* __restrict__ Cf)
{
    extern __shared__ __align__(128) char dsm[];
    const long long zs = (long long)blockIdx.z * SS * SS;
    const long long zd = (long long)blockIdx.z * SS * DD;
    gemm_body<1, 1>(Pf + zs, nullptr, Vtf + zd, nullptr, nullptr,
                    Cf + zd, DD, SS, 1.f, 0, 1,
                    blockIdx.y * BM, blockIdx.x * BN, dsm);
}

__global__ __launch_bounds__(256, 2) void outproj_kernel(
    const f16* __restrict__ Cf, const f16* __restrict__ Wof,
    const float* __restrict__ bo, float* __restrict__ out)
{
    extern __shared__ __align__(128) char dsm[];
    gemm_body<0, 1>(Cf, nullptr, Wof, bo, out, nullptr,
                    DD, DD, 1.f, 0, 0, blockIdx.y * BM, blockIdx.x * BN, dsm);
}

// ---------------------------------------------------------------------------
// Fused split: x -> f16 hi/lo, weights -> single f16; also fills invf.
// ---------------------------------------------------------------------------
constexpr long long N4X = (long long)BB * SS * DD / 4;
constexpr long long N4W = (long long)DD * DD / 4;

__global__ void split_all_kernel(
    const float* __restrict__ x,
    const float* __restrict__ Wq, const float* __restrict__ Wk,
    const float* __restrict__ Wv, const float* __restrict__ Wo,
    f16* __restrict__ xh, f16* __restrict__ xl,
    f16* __restrict__ Wqf, f16* __restrict__ Wkf,
    f16* __restrict__ Wvf, f16* __restrict__ Wof,
    float* __restrict__ invf)
{
    const long long i = (long long)blockIdx.x * blockDim.x + threadIdx.x;
    if (i < DD / 2)
        invf[i] = (float)exp(-(double)i * (9.210340371976184 / (double)(DD / 2)));

    if (i < N4X) {
        float4 v = *reinterpret_cast<const float4*>(x + i * 4);
        f16 h[4], l[4];
        splitf(v.x, h[0], l[0]); splitf(v.y, h[1], l[1]);
        splitf(v.z, h[2], l[2]); splitf(v.w, h[3], l[3]);
        *reinterpret_cast<uint2*>(xh + i * 4) = *reinterpret_cast<uint2*>(h);
        *reinterpret_cast<uint2*>(xl + i * 4) = *reinterpret_cast<uint2*>(l);
        return;
    }
    const float* src;
    f16* dst;
    long long o = i - N4X;
    if (o < N4W)          { src = Wq; dst = Wqf; }
    else if (o < 2 * N4W) { src = Wk; dst = Wkf; o -= N4W; }
    else if (o < 3 * N4W) { src = Wv; dst = Wvf; o -= 2 * N4W; }
    else if (o < 4 * N4W) { src = Wo; dst = Wof; o -= 3 * N4W; }
    else return;

    float4 v = *reinterpret_cast<const float4*>(src + o * 4);
    f16 h[4];
    h[0] = __float2half(v.x); h[1] = __float2half(v.y);
    h[2] = __float2half(v.z); h[3] = __float2half(v.w);
    *reinterpret_cast<uint2*>(dst + o * 4) = *reinterpret_cast<uint2*>(h);
}

// ---------------------------------------------------------------------------
// RoPE: rotate fp32 Q/K pairs; Q -> f16 hi/lo (A-side), K -> single f16.
// ---------------------------------------------------------------------------
__global__ void rope_split_kernel(const float* __restrict__ Q,
                                  const float* __restrict__ Kt,
                                  const float* __restrict__ invf,
                                  f16* __restrict__ Qh, f16* __restrict__ Ql,
                                  f16* __restrict__ Kf)
{
    const int half = DD / 2;
    long long idx = (long long)blockIdx.x * blockDim.x + threadIdx.x;
    const long long total = (long long)BB * SS * half;
    if (idx >= total) return;

    const int i = (int)(idx % half);
    const long long bs = idx / half;
    const int s = (int)(bs % SS);

    const float ang = (float)s * invf[i];
    float sn, cs;
    sincosf(ang, &sn, &cs);

    const long long o = bs * DD;
    const float q1 = Q[o + i], q2 = Q[o + i + half];
    const float k1 = Kt[o + i], k2 = Kt[o + i + half];
    const float qa = q1 * cs - q2 * sn, qb = q1 * sn + q2 * cs;
    const float ka = k1 * cs - k2 * sn, kb = k1 * sn + k2 * cs;

    f16 h, l;
    splitf(qa, h, l); Qh[o + i] = h;        Ql[o + i] = l;
    splitf(qb, h, l); Qh[o + i + half] = h; Ql[o + i + half] = l;
    Kf[o + i] = __float2half(ka);
    Kf[o + i + half] = __float2half(kb);
}

// ---------------------------------------------------------------------------
// Register-resident causal softmax over single-f16 scores (in place).
// ---------------------------------------------------------------------------
__inline__ __device__ float warpMax(float v)
{
    for (int o = 16; o; o >>= 1) v = fmaxf(v, __shfl_xor_sync(0xffffffffu, v, o));
    return v;
}
__inline__ __device__ float warpSum(float v)
{
    for (int o = 16; o; o >>= 1) v += __shfl_xor_sync(0xffffffffu, v, o);
    return v;
}

__global__ __launch_bounds__(256) void softmax_kernel(f16* __restrict__ Pf)
{
    const int i = blockIdx.x;
    const int b = blockIdx.y;
    const long long off = ((long long)b * SS + i) * SS;
    const int len = i + 1;
    const int t = threadIdx.x;
    const int lane = t & 31, w = t >> 5;

    __shared__ float sh[8];
    __shared__ float s_bcast;

    float s[8];
    float m = -INFINITY;
#pragma unroll
    for (int p = 0; p < 8; p++) {
        const int j = t + p * 256;
        if (j < len) {
            s[p] = __half2float(Pf[off + j]);
            m = fmaxf(m, s[p]);
        }
    }
    m = warpMax(m);
    if (lane == 0) sh[w] = m;
    __syncthreads();
    if (t == 0) {
        float mm = sh[0];
        for (int k = 1; k < 8; k++) mm = fmaxf(mm, sh[k]);
        s_bcast = mm;
    }
    __syncthreads();
    m = s_bcast;
    __syncthreads();

    float sum = 0.f;
#pragma unroll
    for (int p = 0; p < 8; p++) {
        const int j = t + p * 256;
        if (j < len) {
            s[p] = expf(s[p] - m);
            sum += s[p];
        }
    }
    sum = warpSum(sum);
    if (lane == 0) sh[w] = sum;
    __syncthreads();
    if (t == 0) {
        float ss = 0.f;
        for (int k = 0; k < 8; k++) ss += sh[k];
        s_bcast = ss;
    }
    __syncthreads();
    const float inv = 1.f / s_bcast;

#pragma unroll
    for (int p = 0; p < 8; p++) {
        const int j = t + p * 256;
        if (j < len) Pf[off + j] = __float2half(s[p] * inv);
    }
}

// ---------------------------------------------------------------------------
extern "C" void kernel_launch(void* const* d_in, const int* in_sizes, int n_in,
                              void* d_out, int out_size)
{
    const float* x  = (const float*)d_in[0];
    // d_in[1] = mask — analytic
    const float* Wq = (const float*)d_in[2];
    const float* bq = (const float*)d_in[3];
    const float* Wk = (const float*)d_in[4];
    const float* bk = (const float*)d_in[5];
    const float* Wv = (const float*)d_in[6];
    const float* bv = (const float*)d_in[7];
    const float* Wo = (const float*)d_in[8];
    const float* bo = (const float*)d_in[9];
    float* out = (float*)d_out;

    float *pQ, *pK, *pInvf;
    cudaGetSymbolAddress((void**)&pQ, g_Q);
    cudaGetSymbolAddress((void**)&pK, g_K);
    cudaGetSymbolAddress((void**)&pInvf, g_invf);

    f16 *xh, *xl, *Wqf, *Wkf, *Wvf, *Wof;
    f16 *Qh, *Ql, *Kf, *Vtf, *Pf, *Cf;
    cudaGetSymbolAddress((void**)&xh, g_xh);   cudaGetSymbolAddress((void**)&xl, g_xl);
    cudaGetSymbolAddress((void**)&Wqf, g_Wqf); cudaGetSymbolAddress((void**)&Wkf, g_Wkf);
    cudaGetSymbolAddress((void**)&Wvf, g_Wvf); cudaGetSymbolAddress((void**)&Wof, g_Wof);
    cudaGetSymbolAddress((void**)&Qh, g_Qh);   cudaGetSymbolAddress((void**)&Ql, g_Ql);
    cudaGetSymbolAddress((void**)&Kf, g_Kf);
    cudaGetSymbolAddress((void**)&Vtf, g_Vtf);
    cudaGetSymbolAddress((void**)&Pf, g_Pf);
    cudaGetSymbolAddress((void**)&Cf, g_Cf);

    cudaFuncSetAttribute(proj3_kernel,   cudaFuncAttributeMaxDynamicSharedMemorySize, SMEM_TOTAL);
    cudaFuncSetAttribute(scores_kernel,  cudaFuncAttributeMaxDynamicSharedMemorySize, SMEM_TOTAL);
    cudaFuncSetAttribute(pv_kernel,      cudaFuncAttributeMaxDynamicSharedMemorySize, SMEM_TOTAL);
    cudaFuncSetAttribute(outproj_kernel, cudaFuncAttributeMaxDynamicSharedMemorySize, SMEM_TOTAL);

    const dim3 blk(256);

    // 1) fused split of x and all weights (+ invf table)
    {
        const long long n4 = N4X + 4 * N4W;
        split_all_kernel<<<(int)((n4 + 255) / 256), 256>>>(
            x, Wq, Wk, Wv, Wo, xh, xl, Wqf, Wkf, Wvf, Wof, pInvf);
    }

    // 2) merged Q/K/V projections
    proj3_kernel<<<dim3(DD / BN, (BB * SS) / BM, 3), blk, SMEM_TOTAL>>>(
        xh, xl, Wqf, bq, pQ, Wkf, bk, pK, Wvf, bv, Vtf);

    // 3) RoPE + split Q / round K
    {
        const long long total = (long long)BB * SS * (DD / 2);
        rope_split_kernel<<<(int)((total + 255) / 256), 256>>>(pQ, pK, pInvf,
                                                               Qh, Ql, Kf);
    }

    // 4) scores = Q K^T / sqrt(D), causal -> single f16 P
    const float scale = 0.022097086912079608f;  // 1/sqrt(2048)
    scores_kernel<<<dim3(SS / BN, SS / BM, BB), blk, SMEM_TOTAL>>>(
        Qh, Ql, Kf, Pf, scale);

    // 5) register softmax on P (in place)
    softmax_kernel<<<dim3(SS, BB), 256>>>(Pf);

    // 6) ctx = P V (triangular K) -> single f16 ctx
    pv_kernel<<<dim3(DD / BN, SS / BM, BB), blk, SMEM_TOTAL>>>(Pf, Vtf, Cf);

    // 7) out = ctx Wo^T + bo
    outproj_kernel<<<dim3(DD / BN, (BB * SS) / BM, 1), blk, SMEM_TOTAL>>>(
        Cf, Wof, bo, out);
}